// round 13
// baseline (speedup 1.0000x reference)
#include <cuda_runtime.h>
#include <math.h>

#define Bq 4
#define Lq 2048
#define Hq 8
#define Dq 64
#define NSLOT 12                 // self + offsets 2^0 .. 2^10
#define SLAB4 (Hq * Dq / 4)      // 128 x 16B chunks per (b,l) slab

// exp(score) = ex2(dot * 0.125 * log2(e))
#define EXC 0.18033688011112042f

__device__ __forceinline__ float ex2f(float x) {
    float r;
    asm("ex2.approx.f32 %0, %1;" : "=f"(r) : "f"(x));
    return r;
}

// One warp per (b, l, head-pair); lane ln owns 16B chunk ln of the 512B
// contiguous head-pair slab (lanes 0-15 even head, 16-31 odd head).
template <bool FULL>
__device__ __forceinline__ void run_query(
    const float4* __restrict__ Q4, const float4* __restrict__ K4,
    const float4* __restrict__ V4, float4* __restrict__ O4,
    int base, int l, int hl)     // hl = lane & 15 (index within half)
{
    const float4 q = Q4[base];

    // ---- phase 1: front-batched K loads (predicated off when invalid) ----
    float v[16];
#pragma unroll
    for (int t = 0; t < NSLOT; t++) {
        const int off = (t == 0) ? 0 : (1 << (t - 1));
        const bool ok = FULL || (off <= l);
        const int kb = base - off * SLAB4;
        float4 k = make_float4(0.f, 0.f, 0.f, 0.f);
        if (ok) k = K4[kb];                        // predicated LDG: no wavefront when off
        v[t] = q.x*k.x + q.y*k.y + q.z*k.z + q.w*k.w;
    }
#pragma unroll
    for (int t = NSLOT; t < 16; t++) v[t] = 0.0f;

    // ---- multi-value butterfly: 15 shfls reduce ALL 16 slots; after this,
    //      lane hl (in each 16-lane half) holds the full dot of slot hl ----
#pragma unroll
    for (int m = 8; m >= 1; m >>= 1) {
#pragma unroll
        for (int j = 0; j < m; j++) {
            const float send = (hl & m) ? v[j] : v[j + m];
            const float other = __shfl_xor_sync(0xffffffffu, send, m);
            v[j] = ((hl & m) ? v[j + m] : v[j]) + other;
        }
    }

    // per-lane validity of slot hl
    bool okl;
    if (FULL) okl = (hl < NSLOT);
    else      okl = (hl == 0) || ((hl < NSLOT) && ((1 << (hl - 1)) <= l));

    // one exp covers all 12 slots (scores ~N(0,1): no overflow)
    const float e = okl ? ex2f(v[0] * EXC) : 0.0f;

    // ---- phase 2: V gathers (predicated) + width-16 prob broadcast.
    //      Denominator summed LOCALLY from the broadcasts (no sum-butterfly,
    //      no serialization between exp and this loop). ----
    float4 acc = {0.f, 0.f, 0.f, 0.f};
    float  sum = 0.0f;
#pragma unroll
    for (int t = 0; t < NSLOT; t++) {
        const int off = (t == 0) ? 0 : (1 << (t - 1));
        const bool ok = FULL || (off <= l);
        const int vb = base - off * SLAB4;
        float4 vv = make_float4(0.f, 0.f, 0.f, 0.f);
        if (ok) vv = V4[vb];                       // predicated LDG + zeroed when off
        const float p = __shfl_sync(0xffffffffu, e, t, 16);  // 0 if slot invalid
        sum += p;
        acc.x += p * vv.x;
        acc.y += p * vv.y;
        acc.z += p * vv.z;
        acc.w += p * vv.w;
    }
    const float inv = 1.0f / sum;
    acc.x *= inv; acc.y *= inv; acc.z *= inv; acc.w *= inv;
    O4[base] = acc;
}

__global__ __launch_bounds__(128) void logsparse_attn_kernel(
    const float4* __restrict__ Q4,
    const float4* __restrict__ K4,
    const float4* __restrict__ V4,
    float4* __restrict__ O4)
{
    const int wid  = (blockIdx.x * blockDim.x + threadIdx.x) >> 5;
    const int lane = threadIdx.x & 31;
    const int g = wid & (Hq / 2 - 1);            // head-pair 0..3
    const int s = wid >> 2;                      // b*L + l
    const int l = s & (Lq - 1);

    const int base = s * SLAB4 + g * 32 + lane;  // 16B-chunk index
    const int hl = lane & 15;

    if (l >= 1024) {
        run_query<true>(Q4, K4, V4, O4, base, l, hl);
    } else {
        run_query<false>(Q4, K4, V4, O4, base, l, hl);
    }
}

extern "C" void kernel_launch(void* const* d_in, const int* in_sizes, int n_in,
                              void* d_out, int out_size)
{
    const float4* Q = (const float4*)d_in[0];
    const float4* K = (const float4*)d_in[1];
    const float4* V = (const float4*)d_in[2];
    float4* O = (float4*)d_out;

    const int total_warps = Bq * Lq * (Hq / 2);      // 32768
    const int threads = 128;
    const int blocks = (total_warps * 32) / threads; // 8192
    logsparse_attn_kernel<<<blocks, threads>>>(Q, K, V, O);
}

// round 14
// speedup vs baseline: 1.0213x; 1.0213x over previous
#include <cuda_runtime.h>
#include <math.h>

#define Bq 4
#define Lq 2048
#define Hq 8
#define Dq 64
#define NSLOT 12                 // self + offsets 2^0 .. 2^10
#define SLAB4 (Hq * Dq / 4)      // 128 x 16B chunks per (b,l) slab

// exp(score) = ex2(dot * 0.125 * log2(e))
#define EXC 0.18033688011112042f

__device__ __forceinline__ float ex2f(float x) {
    float r;
    asm("ex2.approx.f32 %0, %1;" : "=f"(r) : "f"(x));
    return r;
}

// One warp per (b, l, head-pair); lane ln owns 16B chunk ln of the 512B
// contiguous head-pair slab (lanes 0-15 even head, 16-31 odd head).
// NS = number of valid slots, known at compile time per tier (all slots
// 0..NS-1 valid by construction). GEN = generic predicated path for l<64.
template <int NS, bool GEN>
__device__ __forceinline__ void run_query(
    const float4* __restrict__ Q4, const float4* __restrict__ K4,
    const float4* __restrict__ V4, float4* __restrict__ O4,
    int base, int l, int hl)     // hl = lane & 15
{
    const float4 q = Q4[base];

    // ---- phase 1: NS front-batched K loads, per-lane partial dots ----
    float v[16];
#pragma unroll
    for (int t = 0; t < NS; t++) {
        const int off = (t == 0) ? 0 : (1 << (t - 1));
        const bool ok = !GEN || (off <= l);
        const int kb = base - off * SLAB4;       // imm offset in tier paths
        float4 k = make_float4(0.f, 0.f, 0.f, 0.f);
        if (ok) k = K4[kb];                      // unconditional in tier paths
        v[t] = q.x*k.x + q.y*k.y + q.z*k.z + q.w*k.w;
    }
#pragma unroll
    for (int t = NS; t < 16; t++) v[t] = 0.0f;

    // ---- multi-value butterfly: 15 shfls reduce ALL slots; after this,
    //      lane hl (in each 16-lane half) holds the full dot of slot hl ----
#pragma unroll
    for (int m = 8; m >= 1; m >>= 1) {
#pragma unroll
        for (int j = 0; j < m; j++) {
            const float send = (hl & m) ? v[j] : v[j + m];
            const float other = __shfl_xor_sync(0xffffffffu, send, m);
            v[j] = ((hl & m) ? v[j + m] : v[j]) + other;
        }
    }

    // per-lane validity of slot hl (compile-time compare in tier paths)
    bool okl;
    if (!GEN) okl = (hl < NS);
    else      okl = (hl == 0) || ((hl < NSLOT) && ((1 << (hl - 1)) <= l));

    // one exp covers all slots (scores ~N(0,1): no overflow)
    const float e = okl ? ex2f(v[0] * EXC) : 0.0f;

    // ---- phase 2: V gathers + width-16 prob broadcast; denominator summed
    //      locally from the broadcasts (no sum butterfly) ----
    float4 acc = {0.f, 0.f, 0.f, 0.f};
    float  sum = 0.0f;
#pragma unroll
    for (int t = 0; t < NS; t++) {
        const int off = (t == 0) ? 0 : (1 << (t - 1));
        const bool ok = !GEN || (off <= l);
        const int vb = base - off * SLAB4;
        float4 vv = make_float4(0.f, 0.f, 0.f, 0.f);
        if (ok) vv = V4[vb];
        const float p = __shfl_sync(0xffffffffu, e, t, 16);  // 0 if slot invalid
        sum += p;
        acc.x += p * vv.x;
        acc.y += p * vv.y;
        acc.z += p * vv.z;
        acc.w += p * vv.w;
    }
    const float inv = 1.0f / sum;
    acc.x *= inv; acc.y *= inv; acc.z *= inv; acc.w *= inv;
    O4[base] = acc;
}

__global__ __launch_bounds__(128) void logsparse_attn_kernel(
    const float4* __restrict__ Q4,
    const float4* __restrict__ K4,
    const float4* __restrict__ V4,
    float4* __restrict__ O4)
{
    const int wid  = (blockIdx.x * blockDim.x + threadIdx.x) >> 5;
    const int lane = threadIdx.x & 31;
    const int g = wid & (Hq / 2 - 1);            // head-pair 0..3
    const int s = wid >> 2;                      // b*L + l
    const int l = s & (Lq - 1);

    const int base = s * SLAB4 + g * 32 + lane;  // 16B-chunk index
    const int hl = lane & 15;

    // tier dispatch (uniform across the CTA: all 4 warps share l)
    if      (l >= 1024) run_query<12, false>(Q4, K4, V4, O4, base, l, hl);
    else if (l >=  512) run_query<11, false>(Q4, K4, V4, O4, base, l, hl);
    else if (l >=  256) run_query<10, false>(Q4, K4, V4, O4, base, l, hl);
    else if (l >=  128) run_query< 9, false>(Q4, K4, V4, O4, base, l, hl);
    else if (l >=   64) run_query< 8, false>(Q4, K4, V4, O4, base, l, hl);
    else                run_query<12, true >(Q4, K4, V4, O4, base, l, hl);
}

extern "C" void kernel_launch(void* const* d_in, const int* in_sizes, int n_in,
                              void* d_out, int out_size)
{
    const float4* Q = (const float4*)d_in[0];
    const float4* K = (const float4*)d_in[1];
    const float4* V = (const float4*)d_in[2];
    float4* O = (float4*)d_out;

    const int total_warps = Bq * Lq * (Hq / 2);      // 32768
    const int threads = 128;
    const int blocks = (total_warps * 32) / threads; // 8192
    logsparse_attn_kernel<<<blocks, threads>>>(Q, K, V, O);
}